// round 12
// baseline (speedup 1.0000x reference)
#include <cuda_runtime.h>
#include <cuda_bf16.h>
#include <cuda_fp16.h>
#include <cstdint>

// ---------------------------------------------------------------------------
// AttentionDecoderRNN — GB300 (sm_103a)
//
// Round-12: persistent fused recurrence. The 31-step LSTM loop was 62
// serialized graph nodes (~29 us/step, ~900 us); now ONE kernel with a
// software grid barrier (128 CTAs, guaranteed co-resident: 204KB smem ->
// 1 CTA/SM, 128 < 148 SMs). fp32 math unchanged -> rel_err unchanged.
//   - logits GEMM: plain fp16 (K=1024), error 2.7e-4 (validated R9/R11)
//   - gx GEMM: bf16 3-product (K'=1536), error ~7e-6
// ---------------------------------------------------------------------------

#define TB     64
#define TT     31
#define EMB    512
#define HID    1024
#define G4     4096
#define VOC    32000
#define MROWS  (TT * TB)   // 1984
#define MPAD   2048
#define KX     (3 * EMB)   // 1536
#define NCTA   128

// fp32-path state
__device__ float    g_ctx  [TB * HID];
__device__ float    g_bias [G4];
__device__ int      g_rows [MROWS];
__device__ float    g_gbase[TB * G4];
__device__ float    g_gx   [MROWS * G4];
__device__ float    g_h    [TB * HID];
__device__ float    g_hs   [MROWS * HID];
__device__ unsigned g_barrier[TT];

// split operands
__device__ __half        g_WL1[VOC * HID];
__device__ __half        g_Hs1[MPAD * HID];
__device__ __nv_bfloat16 g_Wx3[G4 * KX];
__device__ __nv_bfloat16 g_A3 [MPAD * KX];

// ======================= small helpers =====================================
__device__ __forceinline__ uint32_t smem_u32(const void* p) {
    uint32_t a;
    asm("{ .reg .u64 t; cvta.to.shared.u64 t, %1; cvt.u32.u64 %0, t; }"
        : "=r"(a) : "l"(p));
    return a;
}
__device__ __forceinline__ void ldsm4(uint32_t* r, uint32_t addr) {
    asm volatile("ldmatrix.sync.aligned.m8n8.x4.shared.b16 {%0,%1,%2,%3}, [%4];"
                 : "=r"(r[0]), "=r"(r[1]), "=r"(r[2]), "=r"(r[3]) : "r"(addr));
}
template <bool F16>
__device__ __forceinline__ void mma16816(float* c, const uint32_t* a,
                                         const uint32_t* b) {
    if (F16) {
        asm volatile(
            "mma.sync.aligned.m16n8k16.row.col.f32.f16.f16.f32 "
            "{%0,%1,%2,%3}, {%4,%5,%6,%7}, {%8,%9}, {%0,%1,%2,%3};"
            : "+f"(c[0]), "+f"(c[1]), "+f"(c[2]), "+f"(c[3])
            : "r"(a[0]), "r"(a[1]), "r"(a[2]), "r"(a[3]), "r"(b[0]), "r"(b[1]));
    } else {
        asm volatile(
            "mma.sync.aligned.m16n8k16.row.col.f32.bf16.bf16.f32 "
            "{%0,%1,%2,%3}, {%4,%5,%6,%7}, {%8,%9}, {%0,%1,%2,%3};"
            : "+f"(c[0]), "+f"(c[1]), "+f"(c[2]), "+f"(c[3])
            : "r"(a[0]), "r"(a[1]), "r"(a[2]), "r"(a[3]), "r"(b[0]), "r"(b[1]));
    }
}
__device__ __forceinline__ void cpasync16(uint32_t s, const void* g) {
    asm volatile("cp.async.cg.shared.global [%0], [%1], 16;" :: "r"(s), "l"(g));
}
#define CP_COMMIT() asm volatile("cp.async.commit_group;" ::: "memory")
#define CP_WAIT1()  asm volatile("cp.async.wait_group 1;"  ::: "memory")
#define CP_WAIT0()  asm volatile("cp.async.wait_group 0;"  ::: "memory")

__device__ __forceinline__ unsigned long long pk2(float x) {
    unsigned long long r;
    asm("mov.b64 %0, {%1, %2};" : "=l"(r) : "f"(x), "f"(x));
    return r;
}
__device__ __forceinline__ void unpk2(float& lo, float& hi, unsigned long long v) {
    asm("mov.b64 {%0, %1}, %2;" : "=f"(lo), "=f"(hi) : "l"(v));
}
#define FMA2(d, a, b) asm("fma.rn.f32x2 %0, %1, %2, %0;" : "+l"(d) : "l"(a), "l"(b))

// ======================= split kernels =====================================
__device__ __forceinline__ void split1b(float x, unsigned short& h, unsigned short& l) {
    __nv_bfloat16 hb = __float2bfloat16(x);
    __nv_bfloat16 lb = __float2bfloat16(x - __bfloat162float(hb));
    h = __bfloat16_as_ushort(hb);
    l = __bfloat16_as_ushort(lb);
}
__device__ __forceinline__ void split4b(float4 v, ushort4& h, ushort4& l) {
    split1b(v.x, h.x, l.x); split1b(v.y, h.y, l.y);
    split1b(v.z, h.z, l.z); split1b(v.w, h.w, l.w);
}
__device__ __forceinline__ ushort4 cvt4h(float4 v) {
    ushort4 h;
    h.x = __half_as_ushort(__float2half_rn(v.x));
    h.y = __half_as_ushort(__float2half_rn(v.y));
    h.z = __half_as_ushort(__float2half_rn(v.z));
    h.w = __half_as_ushort(__float2half_rn(v.w));
    return h;
}

__global__ void split_lin(const float* __restrict__ src) {
    int i = blockIdx.x * blockDim.x + threadIdx.x;
    if (i >= VOC * (HID / 4)) return;
    ((ushort4*)g_WL1)[i] = cvt4h(((const float4*)src)[i]);
}

__global__ void split_hs() {
    int i = blockIdx.x * blockDim.x + threadIdx.x;
    if (i >= MPAD * (HID / 4)) return;
    int r = i >> 8;
    float4 v = make_float4(0.f, 0.f, 0.f, 0.f);
    if (r < MROWS) v = ((const float4*)g_hs)[i];
    ((ushort4*)g_Hs1)[i] = cvt4h(v);
}

__global__ void split_wx(const float* __restrict__ src) {
    int i = blockIdx.x * blockDim.x + threadIdx.x;
    if (i >= G4 * (EMB / 4)) return;
    int r = i >> 7, c = (i & 127) * 4;
    float4 v = *(const float4*)(src + (size_t)r * (EMB + HID) + c);
    ushort4 h, l; split4b(v, h, l);
    __nv_bfloat16* row = g_Wx3 + (size_t)r * KX;
    *(ushort4*)(row + c)            = h;
    *(ushort4*)(row + EMB + c)      = l;
    *(ushort4*)(row + 2 * EMB + c)  = h;
}

__global__ void split_emb(const float* __restrict__ embed) {
    int i = blockIdx.x * blockDim.x + threadIdx.x;
    if (i >= MPAD * (EMB / 4)) return;
    int r = i >> 7, c = (i & 127) * 4;
    float4 v = make_float4(0.f, 0.f, 0.f, 0.f);
    if (r < MROWS) v = *(const float4*)(embed + (size_t)g_rows[r] * EMB + c);
    ushort4 h, l; split4b(v, h, l);
    __nv_bfloat16* row = g_A3 + (size_t)r * KX;
    *(ushort4*)(row + c)            = h;
    *(ushort4*)(row + EMB + c)      = h;
    *(ushort4*)(row + 2 * EMB + c)  = l;
}

// ======================= mma.sync GEMM (verified pipeline) =================
#define MM_BM   128
#define MM_BK   32
#define MM_PITCH 80
#define MM_ASZ  (MM_BM * MM_PITCH)
#define MM_STG  (2 * MM_ASZ)
#define MM_SMEM (3 * MM_STG)

template <bool F16>
__global__ __launch_bounds__(256, 2) void mma_gemm(
    const void* __restrict__ Av,
    const void* __restrict__ Bv, int Kp,
    float* __restrict__ C, int ldc, int Mrows,
    const float* __restrict__ bias)
{
    const __half* A = (const __half*)Av;
    const __half* B = (const __half*)Bv;
    extern __shared__ char sm[];
    const uint32_t sb = smem_u32(sm);
    const int tid = threadIdx.x;
    const int wid = tid >> 5, l = tid & 31;
    const int wm = wid & 1, wn = wid >> 1;
    const int bm = blockIdx.x * 128, bn = blockIdx.y * 128;

    const int row0 = tid >> 2, ch = tid & 3;
    const char* gA0 = (const char*)(A + (size_t)(bm + row0) * Kp) + ch * 16;
    const char* gA1 = (const char*)(A + (size_t)(bm + row0 + 64) * Kp) + ch * 16;
    const char* gB0 = (const char*)(B + (size_t)(bn + row0) * Kp) + ch * 16;
    const char* gB1 = (const char*)(B + (size_t)(bn + row0 + 64) * Kp) + ch * 16;
    const uint32_t sA0 = (uint32_t)(row0 * MM_PITCH + ch * 16);
    const uint32_t sA1 = sA0 + 64 * MM_PITCH;

    const int arow = wm * 64 + (l & 7) + ((l >> 3) & 1) * 8;
    const uint32_t aoff = (uint32_t)(arow * MM_PITCH + ((l >> 4) << 3) * 2);
    const int brow = wn * 32 + (l & 7) + ((l >> 4) << 3);
    const uint32_t boff = (uint32_t)(MM_ASZ + brow * MM_PITCH + ((l >> 3) & 1) * 16);

    float acc[4][4][4];
#pragma unroll
    for (int a = 0; a < 4; ++a)
#pragma unroll
        for (int b = 0; b < 4; ++b)
#pragma unroll
            for (int q = 0; q < 4; ++q) acc[a][b][q] = 0.f;

    const int nc = Kp / MM_BK;

#define MM_ISSUE(s, ko) do {                                                 \
    uint32_t _st = sb + (s) * MM_STG;                                        \
    cpasync16(_st + sA0, gA0 + (ko) * 2);                                    \
    cpasync16(_st + sA1, gA1 + (ko) * 2);                                    \
    cpasync16(_st + MM_ASZ + sA0, gB0 + (ko) * 2);                           \
    cpasync16(_st + MM_ASZ + sA1, gB1 + (ko) * 2);                           \
} while (0)

    MM_ISSUE(0, 0);  CP_COMMIT();
    MM_ISSUE(1, 32); CP_COMMIT();

    int cs = 0;
    for (int c = 0; c < nc; ++c) {
        CP_WAIT1();
        __syncthreads();
        const uint32_t st = sb + cs * MM_STG;
#pragma unroll
        for (int kk = 0; kk < 2; ++kk) {
            uint32_t a4[4][4], b4[2][4];
#pragma unroll
            for (int mb = 0; mb < 4; ++mb)
                ldsm4(a4[mb], st + aoff + mb * (16 * MM_PITCH) + kk * 32);
#pragma unroll
            for (int nb = 0; nb < 2; ++nb)
                ldsm4(b4[nb], st + boff + nb * (16 * MM_PITCH) + kk * 32);
#pragma unroll
            for (int mb = 0; mb < 4; ++mb)
#pragma unroll
                for (int j = 0; j < 4; ++j)
                    mma16816<F16>(acc[mb][j], a4[mb], &b4[j >> 1][(j & 1) * 2]);
        }
        __syncthreads();
        const int nx = c + 2;
        const int ns = (cs + 2 >= 3) ? cs - 1 : cs + 2;
        if (nx < nc) MM_ISSUE(ns, nx * 32);
        CP_COMMIT();
        cs = (cs + 1 == 3) ? 0 : cs + 1;
    }
#undef MM_ISSUE

    const int g4 = l >> 2, p2 = l & 3;
#pragma unroll
    for (int mb = 0; mb < 4; ++mb) {
        const int r0 = bm + wm * 64 + mb * 16 + g4;
#pragma unroll
        for (int j = 0; j < 4; ++j) {
            const int col = bn + wn * 32 + j * 8 + p2 * 2;
            float b0 = 0.f, b1 = 0.f;
            if (bias) { b0 = bias[col]; b1 = bias[col + 1]; }
            if (r0 < Mrows) {
                float2 v = make_float2(acc[mb][j][0] + b0, acc[mb][j][1] + b1);
                *(float2*)(C + (size_t)r0 * ldc + col) = v;
            }
            if (r0 + 8 < Mrows) {
                float2 v = make_float2(acc[mb][j][2] + b0, acc[mb][j][3] + b1);
                *(float2*)(C + (size_t)(r0 + 8) * ldc + col) = v;
            }
        }
    }
}

// ======================= persistent fused recurrence =======================
// 128 CTAs x 256 thr; CTA c owns hidden cols [c*8, c*8+8) -> 32 gate cols.
// smem: Wsm 128KB (k-major, conflict-free) + h double-buffer 2x32KB + gates 8KB.
// Per step: gates = h @ Wslice^T (f32x2, h staged via cp.async.cg = L2-coherent),
// CTA-local LSTM update (c in regs), h -> global, grid barrier.
#define LP_WOFF  0                         // Wsm[k*32 + gc], 32768 floats
#define LP_HOFF  32768                     // hsm[2][64][128], 16384 floats
#define LP_GOFF  (32768 + 16384)           // gsm[b*32 + gc], 2048 floats
#define LP_SMEM  ((32768 + 16384 + 2048) * 4)   // 204800 B

__global__ __launch_bounds__(256, 1) void lstm_persistent(
    const float* __restrict__ Whh)
{
    extern __shared__ float smf[];
    float* Wsm = smf + LP_WOFF;
    float* hsm = smf + LP_HOFF;
    float* gsm = smf + LP_GOFF;
    const uint32_t hsm_u = smem_u32(hsm);

    const int tid = threadIdx.x;
    const int jbase = blockIdx.x * 8;

    // ---- preload W slice, transposed to k-major [k][gc] ----
    for (int i = tid; i < 32 * 256; i += 256) {
        int gc = i >> 8;                 // 0..31
        int k4 = (i & 255) * 4;
        int g = gc >> 3, j = gc & 7;
        float4 v = *(const float4*)(Whh + (size_t)(g * 1024 + jbase + j) * HID + k4);
        Wsm[(k4 + 0) * 32 + gc] = v.x;
        Wsm[(k4 + 1) * 32 + gc] = v.y;
        Wsm[(k4 + 2) * 32 + gc] = v.z;
        Wsm[(k4 + 3) * 32 + gc] = v.w;
    }

    // ---- update-phase ownership: 2 elems per thread ----
    const int e0 = tid * 2;
    const int bu = e0 >> 3;              // both elems share b (j = 2k, 2k+1)
    const int ju0 = e0 & 7, ju1 = ju0 + 1;
    float gb[2][4];
#pragma unroll
    for (int g = 0; g < 4; ++g) {
        gb[0][g] = g_gbase[bu * G4 + g * 1024 + jbase + ju0];
        gb[1][g] = g_gbase[bu * G4 + g * 1024 + jbase + ju1];
    }
    float c0 = 0.f, c1 = 0.f;

    // ---- GEMM-phase mapping ----
    const int q  = tid & 7;              // quad: gate cols 4q..4q+3
    const int bp = tid >> 3;             // b pair: b = 2bp, 2bp+1

    __syncthreads();                     // Wsm ready

    for (int t = 0; t < TT; ++t) {
        unsigned long long accA0 = 0, accA1 = 0, accB0 = 0, accB1 = 0;

        if (t > 0) {
            // stage chunk 0 (k in [0,128))
            {
                for (int s = 0; s < 8; ++s) {
                    int i = tid + s * 256;           // f4 index over 64x32
                    int b = i >> 5, x4 = (i & 31) * 4;
                    cpasync16(hsm_u + (uint32_t)(b * 128 + x4) * 4,
                              g_h + b * HID + x4);
                }
                CP_COMMIT();
            }
            for (int kc = 0; kc < 8; ++kc) {
                if (kc + 1 < 8) {
                    uint32_t dst = hsm_u + (uint32_t)(((kc + 1) & 1) * 8192) * 4;
                    const float* src = g_h + (kc + 1) * 128;
                    for (int s = 0; s < 8; ++s) {
                        int i = tid + s * 256;
                        int b = i >> 5, x4 = (i & 31) * 4;
                        cpasync16(dst + (uint32_t)(b * 128 + x4) * 4,
                                  src + b * HID + x4);
                    }
                    CP_COMMIT();
                    CP_WAIT1();
                } else {
                    CP_WAIT0();
                }
                __syncthreads();
                const float* hb = hsm + (kc & 1) * 8192;
                const float* hA = hb + (2 * bp) * 128;
                const float* hB = hA + 128;
                const float* wbase = Wsm + kc * 128 * 32 + 4 * q;
#pragma unroll 4
                for (int kx = 0; kx < 128; kx += 4) {
                    float av[4], bv[4];
                    *(float4*)av = *(const float4*)(hA + kx);
                    *(float4*)bv = *(const float4*)(hB + kx);
#pragma unroll
                    for (int d = 0; d < 4; ++d) {
                        unsigned long long hA2 = pk2(av[d]);
                        unsigned long long hB2 = pk2(bv[d]);
                        const float* wr = wbase + (kx + d) * 32;
                        unsigned long long w0 = *(const unsigned long long*)(wr);
                        unsigned long long w1 = *(const unsigned long long*)(wr + 2);
                        FMA2(accA0, hA2, w0); FMA2(accA1, hA2, w1);
                        FMA2(accB0, hB2, w0); FMA2(accB1, hB2, w1);
                    }
                }
                __syncthreads();         // protect buffer before next restage
            }
        }

        // ---- exchange gates through smem ----
        __syncthreads();
        {
            float x, y;
            unpk2(x, y, accA0);
            gsm[(2 * bp) * 32 + 4 * q]     = x; gsm[(2 * bp) * 32 + 4 * q + 1] = y;
            unpk2(x, y, accA1);
            gsm[(2 * bp) * 32 + 4 * q + 2] = x; gsm[(2 * bp) * 32 + 4 * q + 3] = y;
            unpk2(x, y, accB0);
            gsm[(2 * bp + 1) * 32 + 4 * q]     = x; gsm[(2 * bp + 1) * 32 + 4 * q + 1] = y;
            unpk2(x, y, accB1);
            gsm[(2 * bp + 1) * 32 + 4 * q + 2] = x; gsm[(2 * bp + 1) * 32 + 4 * q + 3] = y;
        }
        __syncthreads();

        // ---- LSTM update (CTA-local) ----
        const float* gxt = g_gx + (size_t)t * (TB * G4) + bu * G4 + jbase;
        {
            float gi = gsm[bu * 32 + 0 + ju0] + gb[0][0] + gxt[ju0];
            float gf = gsm[bu * 32 + 8 + ju0] + gb[0][1] + gxt[1024 + ju0];
            float gg = gsm[bu * 32 + 16 + ju0] + gb[0][2] + gxt[2048 + ju0];
            float go = gsm[bu * 32 + 24 + ju0] + gb[0][3] + gxt[3072 + ju0];
            float i_ = 1.f / (1.f + expf(-gi));
            float f_ = 1.f / (1.f + expf(-gf));
            float o_ = 1.f / (1.f + expf(-go));
            c0 = f_ * c0 + i_ * tanhf(gg);
            float hn = o_ * tanhf(c0);
            g_h[bu * HID + jbase + ju0] = hn;
            g_hs[(size_t)t * (TB * HID) + bu * HID + jbase + ju0] = hn;
        }
        {
            float gi = gsm[bu * 32 + 0 + ju1] + gb[1][0] + gxt[ju1];
            float gf = gsm[bu * 32 + 8 + ju1] + gb[1][1] + gxt[1024 + ju1];
            float gg = gsm[bu * 32 + 16 + ju1] + gb[1][2] + gxt[2048 + ju1];
            float go = gsm[bu * 32 + 24 + ju1] + gb[1][3] + gxt[3072 + ju1];
            float i_ = 1.f / (1.f + expf(-gi));
            float f_ = 1.f / (1.f + expf(-gf));
            float o_ = 1.f / (1.f + expf(-go));
            c1 = f_ * c1 + i_ * tanhf(gg);
            float hn = o_ * tanhf(c1);
            g_h[bu * HID + jbase + ju1] = hn;
            g_hs[(size_t)t * (TB * HID) + bu * HID + jbase + ju1] = hn;
        }

        // ---- grid barrier (release h writes; counters zeroed by prep) ----
        if (t < TT - 1) {
            __syncthreads();
            if (tid == 0) {
                __threadfence();
                atomicAdd(&g_barrier[t], 1u);
                while (atomicAdd(&g_barrier[t], 0u) < (unsigned)NCTA)
                    __nanosleep(64);
            }
            __syncthreads();
        }
    }
}

// ======================= remaining fp32 path ===============================
__global__ void prep_kernel(const int* __restrict__ captions,
                            const float* __restrict__ bih,
                            const float* __restrict__ bhh) {
    int i = blockIdx.x * blockDim.x + threadIdx.x;
    if (i < G4) g_bias[i] = bih[i] + bhh[i];
    if (i < TT) g_barrier[i] = 0u;
    if (i < MROWS) {
        int t = i / TB, b = i % TB;
        g_rows[i] = captions[b * 32 + t];
    }
}

__global__ void ctx_kernel(const float* __restrict__ feat) {
    int idx = blockIdx.x * blockDim.x + threadIdx.x;
    int b = idx >> 10, d = idx & 1023;
    const float* p = feat + (size_t)b * 64 * HID + d;
    float s = 0.f;
#pragma unroll
    for (int ll = 0; ll < 64; ++ll) s += p[ll * HID];
    g_ctx[idx] = s;
}

__global__ __launch_bounds__(256) void sgemm_kernel(
    const float* __restrict__ A, int lda,
    const float* __restrict__ B, int ldb,
    float* __restrict__ C, int ldc,
    int Klen, const float* __restrict__ bias)
{
    __shared__ float As[8][68];
    __shared__ float Bs[8][132];

    const int tid = threadIdx.x;
    const int bm = blockIdx.x * 64;
    const int bn = blockIdx.y * 128;

    const int tn8 = (tid & 15) * 8;
    const int tm4 = (tid >> 4) * 4;

    const float* Aptr = A + (size_t)(bm + (tid >> 1)) * lda + (tid & 1) * 4;
    const float* Bptr = B + (size_t)(bn + (tid >> 1)) * ldb + (tid & 1) * 4;

    float4 aReg = make_float4(0.f, 0.f, 0.f, 0.f), bReg;
    if (tid < 128) aReg = *(const float4*)Aptr;
    bReg = *(const float4*)Bptr;

    unsigned long long acc[4][4];
#pragma unroll
    for (int i = 0; i < 4; ++i)
#pragma unroll
        for (int j = 0; j < 4; ++j) acc[i][j] = 0ull;

    const int nChunks = Klen >> 3;
    for (int kc = 0; kc < nChunks; ++kc) {
        if (tid < 128) {
            int m = tid >> 1, k0 = (tid & 1) * 4;
            As[k0 + 0][m] = aReg.x; As[k0 + 1][m] = aReg.y;
            As[k0 + 2][m] = aReg.z; As[k0 + 3][m] = aReg.w;
        }
        {
            int n = tid >> 1, k0 = (tid & 1) * 4;
            Bs[k0 + 0][n] = bReg.x; Bs[k0 + 1][n] = bReg.y;
            Bs[k0 + 2][n] = bReg.z; Bs[k0 + 3][n] = bReg.w;
        }
        __syncthreads();
        if (kc + 1 < nChunks) {
            if (tid < 128) aReg = *(const float4*)(Aptr + (kc + 1) * 8);
            bReg = *(const float4*)(Bptr + (kc + 1) * 8);
        }
#pragma unroll
        for (int kk = 0; kk < 8; ++kk) {
            float4 av = *(const float4*)&As[kk][tm4];
            unsigned long long aa0 = pk2(av.x), aa1 = pk2(av.y),
                               aa2 = pk2(av.z), aa3 = pk2(av.w);
            const float* brow = &Bs[kk][tn8];
            unsigned long long b0 = *(const unsigned long long*)(brow + 0);
            unsigned long long b1 = *(const unsigned long long*)(brow + 2);
            unsigned long long b2 = *(const unsigned long long*)(brow + 4);
            unsigned long long b3 = *(const unsigned long long*)(brow + 6);
            FMA2(acc[0][0], aa0, b0); FMA2(acc[0][1], aa0, b1);
            FMA2(acc[0][2], aa0, b2); FMA2(acc[0][3], aa0, b3);
            FMA2(acc[1][0], aa1, b0); FMA2(acc[1][1], aa1, b1);
            FMA2(acc[1][2], aa1, b2); FMA2(acc[1][3], aa1, b3);
            FMA2(acc[2][0], aa2, b0); FMA2(acc[2][1], aa2, b1);
            FMA2(acc[2][2], aa2, b2); FMA2(acc[2][3], aa2, b3);
            FMA2(acc[3][0], aa3, b0); FMA2(acc[3][1], aa3, b1);
            FMA2(acc[3][2], aa3, b2); FMA2(acc[3][3], aa3, b3);
        }
        __syncthreads();
    }

    float bv[8];
    if (bias) {
        float4 t0 = *(const float4*)(bias + bn + tn8);
        float4 t1 = *(const float4*)(bias + bn + tn8 + 4);
        bv[0] = t0.x; bv[1] = t0.y; bv[2] = t0.z; bv[3] = t0.w;
        bv[4] = t1.x; bv[5] = t1.y; bv[6] = t1.z; bv[7] = t1.w;
    } else {
#pragma unroll
        for (int q = 0; q < 8; ++q) bv[q] = 0.f;
    }
#pragma unroll
    for (int im = 0; im < 4; ++im) {
        float o[8];
#pragma unroll
        for (int p = 0; p < 4; ++p) unpk2(o[2 * p], o[2 * p + 1], acc[im][p]);
#pragma unroll
        for (int q = 0; q < 8; ++q) o[q] += bv[q];
        float4* cp = reinterpret_cast<float4*>(
            C + (size_t)(bm + tm4 + im) * ldc + bn + tn8);
        cp[0] = make_float4(o[0], o[1], o[2], o[3]);
        cp[1] = make_float4(o[4], o[5], o[6], o[7]);
    }
}

// ---------------------------------------------------------------------------
extern "C" void kernel_launch(void* const* d_in, const int* in_sizes, int n_in,
                              void* d_out, int out_size) {
    const float* features = (const float*)d_in[0];
    const int*   captions = (const int*)  d_in[1];
    const float* embed    = (const float*)d_in[3];
    const float* W_ih     = (const float*)d_in[4];
    const float* W_hh     = (const float*)d_in[5];
    const float* b_ih     = (const float*)d_in[6];
    const float* b_hh     = (const float*)d_in[7];
    const float* lin_W    = (const float*)d_in[10];
    const float* lin_b    = (const float*)d_in[11];
    float* out = (float*)d_out;

    float *p_ctx, *p_gbase, *p_gx, *p_bias;
    cudaGetSymbolAddress((void**)&p_ctx,   g_ctx);
    cudaGetSymbolAddress((void**)&p_gbase, g_gbase);
    cudaGetSymbolAddress((void**)&p_gx,    g_gx);
    cudaGetSymbolAddress((void**)&p_bias,  g_bias);
    void *p_WL1, *p_Hs1, *p_Wx3, *p_A3;
    cudaGetSymbolAddress(&p_WL1, g_WL1);
    cudaGetSymbolAddress(&p_Hs1, g_Hs1);
    cudaGetSymbolAddress(&p_Wx3, g_Wx3);
    cudaGetSymbolAddress(&p_A3,  g_A3);

    cudaFuncSetAttribute(mma_gemm<false>,
                         cudaFuncAttributeMaxDynamicSharedMemorySize, MM_SMEM);
    cudaFuncSetAttribute(mma_gemm<true>,
                         cudaFuncAttributeMaxDynamicSharedMemorySize, MM_SMEM);
    cudaFuncSetAttribute(lstm_persistent,
                         cudaFuncAttributeMaxDynamicSharedMemorySize, LP_SMEM);

    prep_kernel<<<16, 256>>>(captions, b_ih, b_hh);
    ctx_kernel<<<(TB * HID) / 256, 256>>>(features);

    split_lin<<<(VOC * 256) / 256, 256>>>(lin_W);
    split_wx <<<(G4 * 128) / 256, 256>>>(W_ih);
    split_emb<<<(MPAD * 128) / 256, 256>>>(embed);

    // gbase = ctx @ W_ih[:,512:]^T + (b_ih + b_hh)   (fp32)
    sgemm_kernel<<<dim3(1, 32), 256>>>(p_ctx, HID,
                                       W_ih + EMB, EMB + HID,
                                       p_gbase, G4, HID, p_bias);

    // gx = A3 @ Wx3^T   (bf16x3)  M=2048 N=4096 K'=1536
    mma_gemm<false><<<dim3(MPAD / 128, G4 / 128), 256, MM_SMEM>>>(
        p_A3, p_Wx3, KX, p_gx, G4, MROWS, nullptr);

    // fused 31-step recurrence (one launch, grid barrier per step)
    lstm_persistent<<<NCTA, 256, LP_SMEM>>>(W_hh);

    split_hs<<<(MPAD * 256) / 256, 256>>>();

    // out = Hs1 @ WL1^T + lin_b   (fp16, K=1024)  M=2048 N=32000
    mma_gemm<true><<<dim3(MPAD / 128, VOC / 128), 256, MM_SMEM>>>(
        p_Hs1, p_WL1, HID, out, VOC, MROWS, lin_b);
}